// round 6
// baseline (speedup 1.0000x reference)
#include <cuda_runtime.h>
#include <cuda_bf16.h>
#include <cstdint>

// SABR implied vol with BETA=1, R=Q=0 degeneracies:
//   out[e][t][j] = v * B_t(v) * G_j(v)
//   B_t = 1 + t*(c1*v + c2),  c1 = RHO*VOLVOL/4 = -0.0525, c2 = VOLVOL^2*(2-3RHO^2)/24
//   G_j = Phi_j / (Chi_j + 1e-8), Phi_j = 0.3 * L_j / v,  L_j = -ln(m_j)
//   Chi_j = ln( (sqrt(1 + 1.4*Phi + Phi^2) + Phi + 0.7) / 1.7 )
//   j == 2 (m = 1.0): F == K -> G = 1.  price input mathematically unused.
//
// R6: warp-autonomous stage + per-warp bulk TMA drain, no in-loop wait.
//   - deletes 7 LDS.128 + 7 STG.128 per thread (whole L1 store data path)
//   - each warp: 25 STS -> syncwarp -> one 3.2KB cp.async.bulk (lane 0)
//   - single wait_group 0 at block end keeps smem live; no mid-kernel
//     serialization (each warp stages exactly once).

#define BLK 256
#define WARPS (BLK / 32)
#define WTILE 800                 // 32 elems * 25 floats
#define WBYTES (WTILE * 4)        // 3200 B per warp

__device__ __forceinline__ uint32_t smem_u32(const void* p) {
    uint32_t a;
    asm("{ .reg .u64 t; cvta.to.shared.u64 t, %1; cvt.u32.u64 %0, t; }"
        : "=r"(a) : "l"(p));
    return a;
}

__global__ __launch_bounds__(BLK)
void sabr_kernel(const float* __restrict__ vol, float* __restrict__ out, int n)
{
    __shared__ __align__(128) float sm[WARPS][WTILE];   // 25.6 KB

    const int tid  = threadIdx.x;
    const int lane = tid & 31;
    const int wid  = tid >> 5;

    const long long base = (long long)blockIdx.x * BLK;
    const long long we0  = base + wid * 32;
    const int e = (int)we0 + lane;

    // ---- compute 25 outputs ----
    float r[25];
    if (e < n) {
        const float v = vol[e];
        const float slope = fmaf(-0.0525f, v, 0.0019875f);

        const float u = __fdividef(0.3f, v);        // VOLVOL / v
        const float L[4] = { 0.35667494f,   // -ln(0.70)
                             0.16251893f,   // -ln(0.85)
                            -0.13976194f,   // -ln(1.15)
                            -0.26236426f }; // -ln(1.30)
        float g[5];
        g[2] = 1.0f;
        #pragma unroll
        for (int jj = 0; jj < 4; ++jj) {
            const float Phi = u * L[jj];
            // 1 - 2*rho*Phi + Phi^2 = 1 + 1.4*Phi + Phi^2  (always > 0)
            const float h   = fmaf(Phi, Phi, fmaf(1.4f, Phi, 1.0f));
            const float q   = sqrtf(h) + Phi + 0.7f;
            const float Chi = __logf(q * 0.5882353f);    // ln(q/1.7)
            const int j = (jj < 2) ? jj : jj + 1;
            g[j] = __fdividef(Phi, Chi + 1e-8f);
        }
        #pragma unroll
        for (int t = 0; t < 5; ++t) {
            const float vb = v * fmaf((float)t, slope, 1.0f);
            #pragma unroll
            for (int j = 0; j < 5; ++j) r[t * 5 + j] = vb * g[j];
        }
    } else {
        #pragma unroll
        for (int k = 0; k < 25; ++k) r[k] = 0.0f;
    }

    // ---- warp-private transpose: stride 25 (odd) -> conflict-free STS ----
    float* row = &sm[wid][lane * 25];
    #pragma unroll
    for (int k = 0; k < 25; ++k) row[k] = r[k];
    __syncwarp();

    // ---- per-warp bulk drain ----
    if (we0 + 32 <= (long long)n) {
        if (lane == 0) {
            asm volatile("fence.proxy.async.shared::cta;" ::: "memory");
            float* gdst = out + we0 * 25;
            uint32_t saddr = smem_u32(sm[wid]);
            asm volatile(
                "cp.async.bulk.global.shared::cta.bulk_group [%0], [%1], %2;"
                :: "l"(gdst), "r"(saddr), "r"((uint32_t)WBYTES)
                : "memory");
            asm volatile("cp.async.bulk.commit_group;" ::: "memory");
            // keep smem live until the bulk store has read it
            asm volatile("cp.async.bulk.wait_group 0;" ::: "memory");
        }
        __syncwarp();
    } else {
        // ragged tail warp (never hit for n % 32 == 0): scalar bounded flush
        float* __restrict__ gout = out + we0 * 25;
        const long long lim = (long long)n * 25 - we0 * 25;
        #pragma unroll
        for (int k = 0; k < 25; ++k) {
            const int idx = k * 32 + lane;
            if (idx < lim) gout[idx] = sm[wid][idx];
        }
    }
}

extern "C" void kernel_launch(void* const* d_in, const int* in_sizes, int n_in,
                              void* d_out, int out_size)
{
    const float* vol = (const float*)d_in[0];   // metadata order: vol, price
    float* out = (float*)d_out;
    const int n = in_sizes[0];                  // 4096*512 = 2,097,152
    const int blocks = (n + BLK - 1) / BLK;
    sabr_kernel<<<blocks, BLK>>>(vol, out, n);
}

// round 7
// speedup vs baseline: 1.1221x; 1.1221x over previous
#include <cuda_runtime.h>
#include <cuda_bf16.h>

// SABR implied vol with BETA=1, R=Q=0 degeneracies:
//   out[e][t][j] = v * B_t(v) * G_j(v)
//   B_t = 1 + t*(c1*v + c2),  c1 = RHO*VOLVOL/4 = -0.0525, c2 = VOLVOL^2*(2-3RHO^2)/24
//   G_j = Phi_j / (Chi_j + 1e-8), Phi_j = 0.3 * L_j / v,  L_j = -ln(m_j)
//   Chi_j = ln( (sqrt(1 + 1.4*Phi + Phi^2) + Phi + 0.7) / 1.7 )
//   j == 2 (m = 1.0): F == K -> G = 1.  price input mathematically unused.
//
// R7 (final): R2 structure — stage in smem (stride-25, conflict-free),
// one __syncthreads, fire-and-forget float4 __stcs drain. Steady-state
// replay is HBM-write-floor bound (218 MB / iter ≈ 6.6 TB/s ≈ ceiling);
// fire-and-forget STG lets the drain tail overlap the next graph replay,
// which is why this beats all TMA-drain variants in replay. launch_bounds
// (256,8) pins regs <=32 for full 64-warp/SM occupancy.

#define BLK 256

__global__ __launch_bounds__(BLK, 8)
void sabr_kernel(const float* __restrict__ vol, float* __restrict__ out, int n)
{
    __shared__ __align__(16) float sm[BLK * 25];

    const int tid = threadIdx.x;
    const long long base = (long long)blockIdx.x * BLK;
    const int e = (int)base + tid;

    float* row = sm + tid * 25;   // stride 25 (odd) -> bank-conflict-free STS

    if (e < n) {
        const float v = vol[e];

        // B_t = 1 + t*slope
        const float slope = fmaf(-0.0525f, v, 0.0019875f);
        float b[5];
        #pragma unroll
        for (int t = 0; t < 5; ++t) b[t] = fmaf((float)t, slope, 1.0f);

        // G_j for the four m != 1 columns
        const float u = __fdividef(0.3f, v);       // VOLVOL / v
        const float L[4] = { 0.35667494f,   // -ln(0.70)
                             0.16251893f,   // -ln(0.85)
                            -0.13976194f,   // -ln(1.15)
                            -0.26236426f }; // -ln(1.30)
        float g[5];
        g[2] = 1.0f;
        #pragma unroll
        for (int jj = 0; jj < 4; ++jj) {
            const float Phi = u * L[jj];
            // 1 - 2*rho*Phi + Phi^2 = 1 + 1.4*Phi + Phi^2  (always > 0)
            const float h   = fmaf(Phi, Phi, fmaf(1.4f, Phi, 1.0f));
            const float q   = sqrtf(h) + Phi + 0.7f;          // + (Phi - rho)
            const float Chi = __logf(q * 0.5882353f);          // ln(q / 1.7)
            const int j = (jj < 2) ? jj : jj + 1;
            g[j] = __fdividef(Phi, Chi + 1e-8f);
        }

        #pragma unroll
        for (int t = 0; t < 5; ++t) {
            const float vb = v * b[t];
            #pragma unroll
            for (int j = 0; j < 5; ++j)
                row[t * 5 + j] = vb * g[j];
        }
    } else {
        #pragma unroll
        for (int k = 0; k < 25; ++k) row[k] = 0.0f;
    }

    __syncthreads();

    // Flush: linear layout [e][k] in shared == linear output index.
    if (base + BLK <= (long long)n) {
        // Full block: 6400 floats = 1600 float4 = 6 rounds of 256 + 64.
        const float4* __restrict__ s4 = (const float4*)sm;
        float4* __restrict__ g4 = (float4*)(out + base * 25);
        #pragma unroll
        for (int k = 0; k < 6; ++k)
            __stcs(&g4[k * BLK + tid], s4[k * BLK + tid]);
        if (tid < 64)
            __stcs(&g4[6 * BLK + tid], s4[6 * BLK + tid]);
    } else {
        // Tail block (never hit for n % BLK == 0): scalar bounded flush.
        float* __restrict__ gout = out + base * 25;
        const long long lim = (long long)n * 25 - base * 25;
        #pragma unroll
        for (int k = 0; k < 25; ++k) {
            const int idx = k * BLK + tid;
            if (idx < lim) gout[idx] = sm[idx];
        }
    }
}

extern "C" void kernel_launch(void* const* d_in, const int* in_sizes, int n_in,
                              void* d_out, int out_size)
{
    const float* vol = (const float*)d_in[0];   // metadata order: vol, price
    float* out = (float*)d_out;
    const int n = in_sizes[0];                  // 4096*512 = 2,097,152
    const int blocks = (n + BLK - 1) / BLK;
    sabr_kernel<<<blocks, BLK>>>(vol, out, n);
}